// round 12
// baseline (speedup 1.0000x reference)
#include <cuda_runtime.h>
#include <math.h>

// Problem constants: pred/target are [16,1,256,256] fp32.
#define B 16
#define H 256
#define W 256
#define NPIX (B * H * W)   // 1048576
#define NBLK 512           // 16 batches x 32 row-tiles of 8 rows
#define TROWS 8            // rows per phase-A tile
#define TCOLS 8            // columns per phase-B block

typedef unsigned int u32;

// Scratch (device globals — no allocation allowed; zero-init at load).
// g2 transposed [B][W][H] as float bits: |value| = g^2, sign bit = pred-edge.
__device__ u32   g_g2T[NPIX];
__device__ float g_part[NBLK];
__device__ u32   g_tick;    // monotonic completion ticket

// Horizontal 3-AND of one u32 mask word with cross-word carries (OOB==true).
__device__ __forceinline__ u32 hand3(const u32* row, int w) {
    u32 m  = row[w];
    u32 lo = (w > 0) ? (row[w - 1] >> 31) : 1u;
    u32 hi = (w < 7) ? (row[w + 1] & 1u)  : 1u;
    return m & ((m << 1) | lo) & ((m >> 1) | (hi << 31));
}

// Nearest set-bit distance in a 256-bit mask (8 words), position x.
__device__ __forceinline__ int nearest_dist(const u32* __restrict__ mask, int x) {
    int best = 0x7FFFFFFF;
    const int wx = x >> 5, bit = x & 31;
    u32 m = mask[wx] & (0xFFFFFFFFu >> (31 - bit));   // bits <= x
    if (m) {
        best = bit - (31 - __clz(m));
    } else {
        for (int w = wx - 1; w >= 0; --w) {
            u32 mm = mask[w];
            if (mm) { best = x - (w * 32 + 31 - __clz(mm)); break; }
        }
    }
    u32 m2 = mask[wx] & (0xFFFFFFFFu << bit);         // bits >= x
    if (m2) {
        int d = (__ffs(m2) - 1) - bit;
        if (d < best) best = d;
    } else {
        for (int w = wx + 1; w < 8; ++w) {
            u32 mm = mask[w];
            if (mm) { int d = w * 32 + (__ffs(mm) - 1) - x; if (d < best) best = d; break; }
        }
    }
    return best;
}

// ---------------------------------------------------------------------------
// Kernel A: per 8-row tile: edge maps (bitwise), 1D row distance, transposed
// store of g^2 with pred-edge flag in the sign bit. grid = 512 x 256.
// ---------------------------------------------------------------------------
__global__ void __launch_bounds__(256) k_edges(
        const float* __restrict__ pred,
        const float* __restrict__ targ) {
    const int bid  = blockIdx.x;
    const int tid  = threadIdx.x;
    const int lane = tid & 31;
    const int wid  = tid >> 5;

    __shared__ u32 mt[TROWS + 2][8], mp[TROWS + 2][8];   // bool masks (+halo)
    __shared__ u32 te[TROWS][8], pe[TROWS][8];           // edge masks
    __shared__ u32 sg2[TROWS][258];                       // g2|flag (padded)

    const int b  = bid >> 5;
    const int y0 = (bid & 31) * TROWS;
    const int ibase = b * (H * W);

    // Front-batched loads: all halo rows into registers first.
    float tv[TROWS + 2], pv[TROWS + 2];
    #pragma unroll
    for (int r = 0; r < TROWS + 2; ++r) {
        int yy = y0 + r - 1;
        bool inb = (yy >= 0) && (yy < H);
        int off = ibase + yy * W + tid;
        tv[r] = inb ? targ[off] : 1.0f;
        pv[r] = inb ? pred[off] : 1.0f;
    }
    #pragma unroll
    for (int r = 0; r < TROWS + 2; ++r) {
        u32 mtb = __ballot_sync(0xFFFFFFFFu, tv[r] > 0.5f);
        u32 mpb = __ballot_sync(0xFFFFFFFFu, pv[r] > 0.5f);
        if (lane == 0) { mt[r][wid] = mtb; mp[r][wid] = mpb; }
    }
    __syncthreads();

    // Merged horizontal+vertical edge stage: 64 threads, r=tid>>3, w=tid&7.
    // Edge = center & ~(3x3 AND). Redundant hand3 recompute is cheap.
    if (tid < TROWS * 8) {
        int r = tid >> 3, w = tid & 7;
        u32 a9t = hand3(mt[r], w) & hand3(mt[r + 1], w) & hand3(mt[r + 2], w);
        te[r][w] = mt[r + 1][w] & ~a9t;
        u32 a9p = hand3(mp[r], w) & hand3(mp[r + 1], w) & hand3(mp[r + 2], w);
        pe[r][w] = mp[r + 1][w] & ~a9p;
    }
    __syncthreads();

    // Per-pixel 1D row distance; pack g^2 (fp32) + pred-edge flag (sign bit).
    #pragma unroll
    for (int r = 0; r < TROWS; ++r) {
        int best = nearest_dist(te[r], tid);
        float g = (best == 0x7FFFFFFF) ? 1e6f : (float)best;
        u32 peb = (pe[r][tid >> 5] >> (tid & 31)) & 1u;
        sg2[r][tid] = __float_as_uint(g * g) | (peb << 31);
    }
    __syncthreads();

    // Transpose store: thread t -> (y = t&7, xi = t>>3); 8 iterations.
    const int ty = tid & 7, txi = tid >> 3;
    #pragma unroll
    for (int p = 0; p < 8; ++p) {
        int x = p * 32 + txi;
        g_g2T[(b * W + x) * H + y0 + ty] = sg2[ty][x];
    }
}

// ---------------------------------------------------------------------------
// Kernel B: per 8 columns: prefetched r=1..4 min + rare serial tail; masked
// sum of sqrt distances. Last-finished block reduces the 512 partials.
// grid = 512 x 256.
// ---------------------------------------------------------------------------
__global__ void __launch_bounds__(256) k_dist(float* __restrict__ out) {
    const int bid  = blockIdx.x;
    const int tid  = threadIdx.x;
    const int lane = tid & 31;
    const int wid  = tid >> 5;

    __shared__ float craw[TCOLS][H + 8];   // columns, +-4 pad
    __shared__ float wsum[8];
    __shared__ bool  amlast;

    float acc = 0.0f;
    {
        const int colbase = bid * TCOLS;

        // Pad +-4 with huge values (simulate out-of-range y').
        if (tid < 4) {
            #pragma unroll
            for (int k = 0; k < TCOLS; ++k) {
                craw[k][tid] = 1e30f;
                craw[k][H + 4 + tid] = 1e30f;
            }
        }
        // Fill via 64-bit loads: 2 consecutive y per load, 4 loads per thread.
        // Sign bit (pred-edge flag) kept in the stored float.
        #pragma unroll
        for (int k = 0; k < 4; ++k) {
            int idx = tid + k * 256;              // 0..1023
            int c = idx >> 7, y2 = (idx & 127) * 2;
            const float2 v = *(const float2*)&g_g2T[(size_t)(colbase + c) * H + y2];
            *(float2*)&craw[c][4 + y2] = v;
        }
        __syncthreads();

        #pragma unroll
        for (int c = 0; c < TCOLS; ++c) {
            const float* col = &craw[c][4];
            float raw = col[tid];
            if (__float_as_uint(raw) >> 31) {      // pred-edge pixel (sign bit)
                float d2 = fabsf(raw);
                // Independent prefetch of r=1..4 (fabs folds into operand mods).
                float m1 = fminf(fabsf(col[tid - 1]), fabsf(col[tid + 1]));
                float m2 = fminf(fabsf(col[tid - 2]), fabsf(col[tid + 2]));
                float m3 = fminf(fabsf(col[tid - 3]), fabsf(col[tid + 3]));
                float m4 = fminf(fabsf(col[tid - 4]), fabsf(col[tid + 4]));
                d2 = fminf(d2, fminf(fminf(1.0f + m1, 4.0f + m2),
                                     fminf(9.0f + m3, 16.0f + m4)));
                if (d2 > 25.0f) {                  // rare serial tail, exact pruning
                    for (int r = 5; r < H; ++r) {
                        float rr = (float)(r * r); // exact in fp32 for r <= 255
                        if (rr >= d2) break;
                        int ym = tid - r, yp = tid + r;
                        if (ym >= 0) d2 = fminf(d2, rr + fabsf(col[ym]));
                        if (yp < H)  d2 = fminf(d2, rr + fabsf(col[yp]));
                    }
                }
                acc += sqrtf(d2);
            }
        }
    }

    // Block reduction (fp32, fixed order -> deterministic).
    #pragma unroll
    for (int o = 16; o; o >>= 1) acc += __shfl_down_sync(0xFFFFFFFFu, acc, o);
    if (lane == 0) wsum[wid] = acc;
    __syncthreads();
    if (tid == 0) {
        float s = wsum[0] + wsum[1] + wsum[2] + wsum[3]
                + wsum[4] + wsum[5] + wsum[6] + wsum[7];
        g_part[bid] = s;
        __threadfence();
        u32 t = atomicAdd(&g_tick, 1u);   // monotonic across graph replays
        amlast = ((t % NBLK) == (NBLK - 1));
    }
    __syncthreads();

    // Last-finished block reduces all partials (fixed order -> deterministic).
    if (amlast) {
        float v = g_part[tid] + g_part[tid + 256];
        #pragma unroll
        for (int o = 16; o; o >>= 1) v += __shfl_down_sync(0xFFFFFFFFu, v, o);
        if (lane == 0) wsum[wid] = v;
        __syncthreads();
        if (tid == 0) {
            double s = 0.0;
            #pragma unroll
            for (int i = 0; i < 8; ++i) s += (double)wsum[i];
            out[0] = (float)(s / (double)NPIX);
        }
    }
}

extern "C" void kernel_launch(void* const* d_in, const int* in_sizes, int n_in,
                              void* d_out, int out_size) {
    const float* pred = (const float*)d_in[0];
    const float* targ = (const float*)d_in[1];
    float* out = (float*)d_out;

    k_edges<<<NBLK, 256>>>(pred, targ);
    k_dist<<<NBLK, 256>>>(out);
}

// round 13
// speedup vs baseline: 1.1271x; 1.1271x over previous
#include <cuda_runtime.h>
#include <math.h>

// Problem constants: pred/target are [16,1,256,256] fp32.
#define B 16
#define H 256
#define W 256
#define NPIX (B * H * W)   // 1048576
#define NBLK 512           // 16 batches x 32 row-tiles of 8 rows
#define TROWS 8            // rows per phase-A tile
#define TCOLS 8            // columns per phase-B block

typedef unsigned int u32;

// Scratch (device globals — no allocation allowed; zero-init at load).
// g2 transposed [B][W][H] as float bits: |value| = g^2, sign bit = pred-edge.
__device__ u32   g_g2T[NPIX];
__device__ float g_part[NBLK];
__device__ u32   g_bar;     // monotonic grid-barrier counter
__device__ u32   g_tick;    // monotonic completion ticket

// ---------------------------------------------------------------------------
// Grid barrier: monotonic counter. Safe: all NBLK blocks co-resident
// (launch_bounds(256,4) caps regs at 64 -> 4 blocks/SM; 512 <= 148*4).
// ---------------------------------------------------------------------------
__device__ __forceinline__ void grid_barrier() {
    __syncthreads();
    if (threadIdx.x == 0) {
        __threadfence();
        u32 t = atomicAdd(&g_bar, 1u);
        u32 target = (t / NBLK + 1u) * NBLK;
        while (*(volatile u32*)&g_bar < target) { __nanosleep(64); }
        __threadfence();
    }
    __syncthreads();
}

// Horizontal 3-AND of one u32 mask word with cross-word carries (OOB==true).
__device__ __forceinline__ u32 hand3(const u32* row, int w) {
    u32 m  = row[w];
    u32 lo = (w > 0) ? (row[w - 1] >> 31) : 1u;
    u32 hi = (w < 7) ? (row[w + 1] & 1u)  : 1u;
    return m & ((m << 1) | lo) & ((m >> 1) | (hi << 31));
}

// Nearest set-bit distance in a 256-bit mask (8 words), position x.
__device__ __forceinline__ int nearest_dist(const u32* __restrict__ mask, int x) {
    int best = 0x7FFFFFFF;
    const int wx = x >> 5, bit = x & 31;
    u32 m = mask[wx] & (0xFFFFFFFFu >> (31 - bit));   // bits <= x
    if (m) {
        best = bit - (31 - __clz(m));
    } else {
        for (int w = wx - 1; w >= 0; --w) {
            u32 mm = mask[w];
            if (mm) { best = x - (w * 32 + 31 - __clz(mm)); break; }
        }
    }
    u32 m2 = mask[wx] & (0xFFFFFFFFu << bit);         // bits >= x
    if (m2) {
        int d = (__ffs(m2) - 1) - bit;
        if (d < best) best = d;
    } else {
        for (int w = wx + 1; w < 8; ++w) {
            u32 mm = mask[w];
            if (mm) { int d = w * 32 + (__ffs(mm) - 1) - x; if (d < best) best = d; break; }
        }
    }
    return best;
}

// ---------------------------------------------------------------------------
// Single fused kernel. grid = 512 blocks x 256 threads.
// Phase A: 8-row tile: edges (bitwise), 1D row distance, transpose-store.
// Global barrier, then
// Phase B: 8 columns, 3 passes: branchless r<=4 min (high ILP), rare exact
// tail (warp-voted), branchless sqrt+accumulate.
// Finalize: last-finished block reduces the 512 partials (fixed order).
// ---------------------------------------------------------------------------
__global__ void __launch_bounds__(256, 4) edge_loss_fused(
        const float* __restrict__ pred,
        const float* __restrict__ targ,
        float* __restrict__ out) {
    const int bid  = blockIdx.x;          // 0..511
    const int tid  = threadIdx.x;         // 0..255
    const int lane = tid & 31;
    const int wid  = tid >> 5;

    __shared__ u32 mt[TROWS + 2][8], mp[TROWS + 2][8];   // bool masks (+halo)
    __shared__ u32 te[TROWS][8], pe[TROWS][8];           // edge masks
    __shared__ u32 sg2[TROWS][258];                       // g2|flag (padded)
    __shared__ __align__(16) float craw[TCOLS][H + 8];    // columns, +-4 pad
    __shared__ float wsum[8];
    __shared__ bool  amlast;

    // ===================== Phase A: rows =====================
    {
        const int b  = bid >> 5;
        const int y0 = (bid & 31) * TROWS;
        const int ibase = b * (H * W);

        // Front-batched loads: all halo rows into registers first.
        float tv[TROWS + 2], pv[TROWS + 2];
        #pragma unroll
        for (int r = 0; r < TROWS + 2; ++r) {
            int yy = y0 + r - 1;
            bool inb = (yy >= 0) && (yy < H);
            int off = ibase + yy * W + tid;
            tv[r] = inb ? targ[off] : 1.0f;
            pv[r] = inb ? pred[off] : 1.0f;
        }
        #pragma unroll
        for (int r = 0; r < TROWS + 2; ++r) {
            u32 mtb = __ballot_sync(0xFFFFFFFFu, tv[r] > 0.5f);
            u32 mpb = __ballot_sync(0xFFFFFFFFu, pv[r] > 0.5f);
            if (lane == 0) { mt[r][wid] = mtb; mp[r][wid] = mpb; }
        }
        __syncthreads();

        // Merged horizontal+vertical edge stage: 64 threads, r=tid>>3, w=tid&7.
        if (tid < TROWS * 8) {
            int r = tid >> 3, w = tid & 7;
            u32 a9t = hand3(mt[r], w) & hand3(mt[r + 1], w) & hand3(mt[r + 2], w);
            te[r][w] = mt[r + 1][w] & ~a9t;
            u32 a9p = hand3(mp[r], w) & hand3(mp[r + 1], w) & hand3(mp[r + 2], w);
            pe[r][w] = mp[r + 1][w] & ~a9p;
        }
        __syncthreads();

        // Per-pixel 1D row distance; pack g^2 (fp32) + pred-edge flag (sign bit).
        #pragma unroll
        for (int r = 0; r < TROWS; ++r) {
            int best = nearest_dist(te[r], tid);
            float g = (best == 0x7FFFFFFF) ? 1e6f : (float)best;
            u32 peb = (pe[r][tid >> 5] >> (tid & 31)) & 1u;
            sg2[r][tid] = __float_as_uint(g * g) | (peb << 31);
        }
        __syncthreads();

        // Transpose store: thread t -> (y = t&7, xi = t>>3); 8 iterations.
        const int ty = tid & 7, txi = tid >> 3;
        #pragma unroll
        for (int p = 0; p < 8; ++p) {
            int x = p * 32 + txi;
            g_g2T[(b * W + x) * H + y0 + ty] = sg2[ty][x];
        }
    }

    grid_barrier();

    // ===================== Phase B: columns =====================
    float acc = 0.0f;
    {
        const int colbase = bid * TCOLS;   // columns of batch b = bid>>5

        // Pad +-4 with huge values (simulate out-of-range y').
        if (tid < 4) {
            #pragma unroll
            for (int k = 0; k < TCOLS; ++k) {
                craw[k][tid] = 1e30f;
                craw[k][H + 4 + tid] = 1e30f;
            }
        }
        // Fill via 128-bit loads: 4 consecutive y per load, 2 loads per thread.
        // Sign bit (pred-edge flag) kept in the stored float.
        #pragma unroll
        for (int k = 0; k < 2; ++k) {
            int idx = tid + k * 256;              // 0..511
            int c = idx >> 6, y4 = (idx & 63) * 4;
            const float4 v = *(const float4*)&g_g2T[(size_t)(colbase + c) * H + y4];
            *(float4*)&craw[c][4 + y4] = v;
        }
        __syncthreads();

        // Pass 1: branchless r<=4 candidate min for ALL 8 columns (high ILP).
        float d2v[TCOLS];
        u32 actmask = 0;
        #pragma unroll
        for (int c = 0; c < TCOLS; ++c) {
            const float* col = &craw[c][4];
            float raw = col[tid];
            actmask |= (__float_as_uint(raw) >> 31) << c;
            float m1 = fminf(fabsf(col[tid - 1]), fabsf(col[tid + 1]));
            float m2 = fminf(fabsf(col[tid - 2]), fabsf(col[tid + 2]));
            float m3 = fminf(fabsf(col[tid - 3]), fabsf(col[tid + 3]));
            float m4 = fminf(fabsf(col[tid - 4]), fabsf(col[tid + 4]));
            d2v[c] = fminf(fabsf(raw),
                           fminf(fminf(1.0f + m1, 4.0f + m2),
                                 fminf(9.0f + m3, 16.0f + m4)));
        }

        // Pass 2: rare exact serial tail, warp-voted per column.
        #pragma unroll
        for (int c = 0; c < TCOLS; ++c) {
            bool need = ((actmask >> c) & 1u) && (d2v[c] > 25.0f);
            if (__any_sync(0xFFFFFFFFu, need)) {
                if (need) {
                    const float* col = &craw[c][4];
                    float d2 = d2v[c];
                    for (int r = 5; r < H; ++r) {
                        float rr = (float)(r * r);  // exact in fp32 for r <= 255
                        if (rr >= d2) break;
                        int ym = tid - r, yp = tid + r;
                        if (ym >= 0) d2 = fminf(d2, rr + fabsf(col[ym]));
                        if (yp < H)  d2 = fminf(d2, rr + fabsf(col[yp]));
                    }
                    d2v[c] = d2;
                }
            }
        }

        // Pass 3: branchless accumulate.
        #pragma unroll
        for (int c = 0; c < TCOLS; ++c)
            acc += ((actmask >> c) & 1u) ? sqrtf(d2v[c]) : 0.0f;
    }

    // Block reduction (fp32, fixed order -> deterministic).
    #pragma unroll
    for (int o = 16; o; o >>= 1) acc += __shfl_down_sync(0xFFFFFFFFu, acc, o);
    if (lane == 0) wsum[wid] = acc;
    __syncthreads();
    if (tid == 0) {
        float s = wsum[0] + wsum[1] + wsum[2] + wsum[3]
                + wsum[4] + wsum[5] + wsum[6] + wsum[7];
        g_part[bid] = s;
        __threadfence();
        u32 t = atomicAdd(&g_tick, 1u);   // monotonic across graph replays
        amlast = ((t % NBLK) == (NBLK - 1));
    }
    __syncthreads();

    // Last-finished block reduces all partials (fixed order -> deterministic).
    if (amlast) {
        float v = g_part[tid] + g_part[tid + 256];
        #pragma unroll
        for (int o = 16; o; o >>= 1) v += __shfl_down_sync(0xFFFFFFFFu, v, o);
        if (lane == 0) wsum[wid] = v;
        __syncthreads();
        if (tid == 0) {
            double s = 0.0;
            #pragma unroll
            for (int i = 0; i < 8; ++i) s += (double)wsum[i];
            out[0] = (float)(s / (double)NPIX);
        }
    }
}

extern "C" void kernel_launch(void* const* d_in, const int* in_sizes, int n_in,
                              void* d_out, int out_size) {
    const float* pred = (const float*)d_in[0];
    const float* targ = (const float*)d_in[1];
    float* out = (float*)d_out;

    edge_loss_fused<<<NBLK, 256>>>(pred, targ, out);
}

// round 14
// speedup vs baseline: 1.2239x; 1.0858x over previous
#include <cuda_runtime.h>
#include <math.h>

// Problem constants: pred/target are [16,1,256,256] fp32.
#define B 16
#define H 256
#define W 256
#define NPIX (B * H * W)   // 1048576
#define NBLK 512           // 16 batches x 32 row-tiles of 8 rows
#define TROWS 8            // rows per phase-A tile
#define TCOLS 8            // columns per phase-B block

typedef unsigned int u32;
typedef unsigned long long u64;

// Scratch (device globals — no allocation allowed; zero-init at load).
// g2 transposed [B][W][H] as float bits: |value| = g^2, sign bit = pred-edge.
__device__ u32   g_g2T[NPIX];
__device__ float g_part[NBLK];
__device__ u32   g_bar;     // monotonic grid-barrier counter
__device__ u32   g_tick;    // monotonic completion ticket

// ---------------------------------------------------------------------------
// Grid barrier: monotonic counter. Safe: all NBLK blocks co-resident
// (launch_bounds(256,4) -> 4 blocks/SM feasible; 512 <= 148*4).
// ---------------------------------------------------------------------------
__device__ __forceinline__ void grid_barrier() {
    __syncthreads();
    if (threadIdx.x == 0) {
        __threadfence();
        u32 t = atomicAdd(&g_bar, 1u);
        u32 target = (t / NBLK + 1u) * NBLK;
        while (*(volatile u32*)&g_bar < target) { __nanosleep(64); }
        __threadfence();
    }
    __syncthreads();
}

// Horizontal 3-AND of one u32 mask word with cross-word carries (OOB==true).
__device__ __forceinline__ u32 hand3(const u32* row, int w) {
    u32 m  = row[w];
    u32 lo = (w > 0) ? (row[w - 1] >> 31) : 1u;
    u32 hi = (w < 7) ? (row[w + 1] & 1u)  : 1u;
    return m & ((m << 1) | lo) & ((m >> 1) | (hi << 31));
}

// Full-scan nearest set-bit distance (fallback; mask = 8 words).
__device__ __forceinline__ int nearest_full(const u32* __restrict__ mask, int x) {
    int best = 0x7FFFFFFF;
    const int wx = x >> 5, bit = x & 31;
    u32 m = mask[wx] & (0xFFFFFFFFu >> (31 - bit));
    if (m) {
        best = bit - (31 - __clz(m));
    } else {
        for (int w = wx - 1; w >= 0; --w) {
            u32 mm = mask[w];
            if (mm) { best = x - (w * 32 + 31 - __clz(mm)); break; }
        }
    }
    u32 m2 = mask[wx] & (0xFFFFFFFFu << bit);
    if (m2) {
        int d = (__ffs(m2) - 1) - bit;
        if (d < best) best = d;
    } else {
        for (int w = wx + 1; w < 8; ++w) {
            u32 mm = mask[w];
            if (mm) { int d = w * 32 + (__ffs(mm) - 1) - x; if (d < best) best = d; break; }
        }
    }
    return best;
}

// ---------------------------------------------------------------------------
// Single fused kernel. grid = 512 blocks x 256 threads.
// Phase A: 8-row tile: edges (bitwise), windowed O(1) 1D row distance,
// transpose-store. Global barrier, then
// Phase B: 8 columns, branchless r<=4 min + rare exact tail + sum.
// Finalize: last-finished block reduces the 512 partials (fixed order).
// ---------------------------------------------------------------------------
__global__ void __launch_bounds__(256, 4) edge_loss_fused(
        const float* __restrict__ pred,
        const float* __restrict__ targ,
        float* __restrict__ out) {
    const int bid  = blockIdx.x;          // 0..511
    const int tid  = threadIdx.x;         // 0..255
    const int lane = tid & 31;
    const int wid  = tid >> 5;

    __shared__ u32 mt[TROWS + 2][8], mp[TROWS + 2][8];   // bool masks (+halo)
    __shared__ u32 tepad[TROWS][10];                      // target-edge masks, 0-padded
    __shared__ u32 pe[TROWS][8];                          // pred-edge masks
    __shared__ u32 sg2[TROWS][258];                       // g2|flag (padded)
    __shared__ __align__(16) float craw[TCOLS][H + 8];    // columns, +-4 pad
    __shared__ float wsum[8];
    __shared__ bool  amlast;

    // ===================== Phase A: rows =====================
    {
        const int b  = bid >> 5;
        const int y0 = (bid & 31) * TROWS;
        const int ibase = b * (H * W);

        // Front-batched loads: all halo rows into registers first.
        float tv[TROWS + 2], pv[TROWS + 2];
        #pragma unroll
        for (int r = 0; r < TROWS + 2; ++r) {
            int yy = y0 + r - 1;
            bool inb = (yy >= 0) && (yy < H);
            int off = ibase + yy * W + tid;
            tv[r] = inb ? targ[off] : 1.0f;
            pv[r] = inb ? pred[off] : 1.0f;
        }
        #pragma unroll
        for (int r = 0; r < TROWS + 2; ++r) {
            u32 mtb = __ballot_sync(0xFFFFFFFFu, tv[r] > 0.5f);
            u32 mpb = __ballot_sync(0xFFFFFFFFu, pv[r] > 0.5f);
            if (lane == 0) { mt[r][wid] = mtb; mp[r][wid] = mpb; }
        }
        __syncthreads();

        // Merged horizontal+vertical edge stage: 64 threads, r=tid>>3, w=tid&7.
        if (tid < TROWS * 8) {
            int r = tid >> 3, w = tid & 7;
            u32 a9t = hand3(mt[r], w) & hand3(mt[r + 1], w) & hand3(mt[r + 2], w);
            tepad[r][w + 1] = mt[r + 1][w] & ~a9t;
            u32 a9p = hand3(mp[r], w) & hand3(mp[r + 1], w) & hand3(mp[r + 2], w);
            pe[r][w] = mp[r + 1][w] & ~a9p;
        }
        if (tid < TROWS) { tepad[tid][0] = 0u; tepad[tid][9] = 0u; }  // pad words
        __syncthreads();

        // Per-pixel 1D row distance via O(1) 64-bit funnel window.
        // Left window covers distances 0..(32+bit), right covers 0..(63-bit);
        // both >= 32, so any result <= 32 is exact. Fallback is warp-voted.
        const int wx = tid >> 5, bit = tid & 31;
        #pragma unroll
        for (int r = 0; r < TROWS; ++r) {
            u32 mlo = tepad[r][wx];          // word wx-1
            u32 mc  = tepad[r][wx + 1];      // word wx
            u32 mhi = tepad[r][wx + 2];      // word wx+1
            u64 lo = ((u64)mc << 32) | mlo;  // bit (32+bit) == pixel x
            u64 hi = ((u64)mhi << 32) | mc;  // bit bit == pixel x
            int dl = __clzll(lo << (31 - bit));            // 64 if empty
            u64 rsh = hi >> bit;
            int dr = rsh ? (__ffsll(rsh) - 1) : 1000;
            int d = min(dl, dr);
            bool need = (d > 32);                          // window inconclusive
            if (__any_sync(0xFFFFFFFFu, need)) {
                if (need) d = nearest_full(&tepad[r][1], tid);
            }
            float g = (d >= 1000) ? 1e6f : (float)d;       // d==1000 => no edge found
            u32 peb = (pe[r][wx] >> bit) & 1u;
            sg2[r][tid] = __float_as_uint(g * g) | (peb << 31);
        }
        __syncthreads();

        // Transpose store: thread t -> (y = t&7, xi = t>>3); 8 iterations.
        const int ty = tid & 7, txi = tid >> 3;
        #pragma unroll
        for (int p = 0; p < 8; ++p) {
            int x = p * 32 + txi;
            g_g2T[(b * W + x) * H + y0 + ty] = sg2[ty][x];
        }
    }

    grid_barrier();

    // ===================== Phase B: columns =====================
    float acc = 0.0f;
    {
        const int colbase = bid * TCOLS;   // columns of batch b = bid>>5

        // Pad +-4 with huge values (simulate out-of-range y').
        if (tid < 4) {
            #pragma unroll
            for (int k = 0; k < TCOLS; ++k) {
                craw[k][tid] = 1e30f;
                craw[k][H + 4 + tid] = 1e30f;
            }
        }
        // Fill via 128-bit loads: 4 consecutive y per load, 2 loads per thread.
        #pragma unroll
        for (int k = 0; k < 2; ++k) {
            int idx = tid + k * 256;              // 0..511
            int c = idx >> 6, y4 = (idx & 63) * 4;
            const float4 v = *(const float4*)&g_g2T[(size_t)(colbase + c) * H + y4];
            *(float4*)&craw[c][4 + y4] = v;
        }
        __syncthreads();

        // Pass 1: branchless r<=4 candidate min for ALL 8 columns (high ILP).
        float d2v[TCOLS];
        u32 actmask = 0;
        #pragma unroll
        for (int c = 0; c < TCOLS; ++c) {
            const float* col = &craw[c][4];
            float raw = col[tid];
            actmask |= (__float_as_uint(raw) >> 31) << c;
            float m1 = fminf(fabsf(col[tid - 1]), fabsf(col[tid + 1]));
            float m2 = fminf(fabsf(col[tid - 2]), fabsf(col[tid + 2]));
            float m3 = fminf(fabsf(col[tid - 3]), fabsf(col[tid + 3]));
            float m4 = fminf(fabsf(col[tid - 4]), fabsf(col[tid + 4]));
            d2v[c] = fminf(fabsf(raw),
                           fminf(fminf(1.0f + m1, 4.0f + m2),
                                 fminf(9.0f + m3, 16.0f + m4)));
        }

        // Pass 2: rare exact serial tail, warp-voted per column.
        #pragma unroll
        for (int c = 0; c < TCOLS; ++c) {
            bool need = ((actmask >> c) & 1u) && (d2v[c] > 25.0f);
            if (__any_sync(0xFFFFFFFFu, need)) {
                if (need) {
                    const float* col = &craw[c][4];
                    float d2 = d2v[c];
                    for (int r = 5; r < H; ++r) {
                        float rr = (float)(r * r);  // exact in fp32 for r <= 255
                        if (rr >= d2) break;
                        int ym = tid - r, yp = tid + r;
                        if (ym >= 0) d2 = fminf(d2, rr + fabsf(col[ym]));
                        if (yp < H)  d2 = fminf(d2, rr + fabsf(col[yp]));
                    }
                    d2v[c] = d2;
                }
            }
        }

        // Pass 3: branchless accumulate.
        #pragma unroll
        for (int c = 0; c < TCOLS; ++c)
            acc += ((actmask >> c) & 1u) ? sqrtf(d2v[c]) : 0.0f;
    }

    // Block reduction (fp32, fixed order -> deterministic).
    #pragma unroll
    for (int o = 16; o; o >>= 1) acc += __shfl_down_sync(0xFFFFFFFFu, acc, o);
    if (lane == 0) wsum[wid] = acc;
    __syncthreads();
    if (tid == 0) {
        float s = wsum[0] + wsum[1] + wsum[2] + wsum[3]
                + wsum[4] + wsum[5] + wsum[6] + wsum[7];
        g_part[bid] = s;
        __threadfence();
        u32 t = atomicAdd(&g_tick, 1u);   // monotonic across graph replays
        amlast = ((t % NBLK) == (NBLK - 1));
    }
    __syncthreads();

    // Last-finished block reduces all partials (fixed order -> deterministic).
    if (amlast) {
        float v = g_part[tid] + g_part[tid + 256];
        #pragma unroll
        for (int o = 16; o; o >>= 1) v += __shfl_down_sync(0xFFFFFFFFu, v, o);
        if (lane == 0) wsum[wid] = v;
        __syncthreads();
        if (tid == 0) {
            double s = 0.0;
            #pragma unroll
            for (int i = 0; i < 8; ++i) s += (double)wsum[i];
            out[0] = (float)(s / (double)NPIX);
        }
    }
}

extern "C" void kernel_launch(void* const* d_in, const int* in_sizes, int n_in,
                              void* d_out, int out_size) {
    const float* pred = (const float*)d_in[0];
    const float* targ = (const float*)d_in[1];
    float* out = (float*)d_out;

    edge_loss_fused<<<NBLK, 256>>>(pred, targ, out);
}

// round 15
// speedup vs baseline: 1.3695x; 1.1190x over previous
#include <cuda_runtime.h>
#include <math.h>

// Problem constants: pred/target are [16,1,256,256] fp32.
#define B 16
#define H 256
#define W 256
#define NPIX (B * H * W)   // 1048576
#define NBLK 512           // 16 batches x 32 row-strips of 8 rows
#define TROWS 8            // pixel rows per block
#define MARG 12            // vertical mask margin (strip-exact radius)
#define SROWS (TROWS + 2 * MARG)   // 32 strip mask rows
#define INROWS (SROWS + 2)         // 34 target input rows

typedef unsigned int u32;
typedef unsigned long long u64;

// Device globals (no allocation allowed; zero-init at load).
__device__ float g_part[NBLK];
__device__ u32   g_tick;    // monotonic completion ticket

// Horizontal 3-AND of one u32 mask word with cross-word carries (OOB==true).
__device__ __forceinline__ u32 hand3(const u32* row, int w) {
    u32 m  = row[w];
    u32 lo = (w > 0) ? (row[w - 1] >> 31) : 1u;
    u32 hi = (w < 7) ? (row[w + 1] & 1u)  : 1u;
    return m & ((m << 1) | lo) & ((m >> 1) | (hi << 31));
}

// Exact full-scan nearest set-bit distance (8-word mask) or INT_MAX if empty.
__device__ __forceinline__ int nearest_full(const u32* __restrict__ mask, int x) {
    int best = 0x7FFFFFFF;
    const int wx = x >> 5, bit = x & 31;
    u32 m = mask[wx] & (0xFFFFFFFFu >> (31 - bit));
    if (m) {
        best = bit - (31 - __clz(m));
    } else {
        for (int w = wx - 1; w >= 0; --w) {
            u32 mm = mask[w];
            if (mm) { best = x - (w * 32 + 31 - __clz(mm)); break; }
        }
    }
    u32 m2 = mask[wx] & (0xFFFFFFFFu << bit);
    if (m2) {
        int d = (__ffs(m2) - 1) - bit;
        if (d < best) best = d;
    } else {
        for (int w = wx + 1; w < 8; ++w) {
            u32 mm = mask[w];
            if (mm) { int d = w * 32 + (__ffs(mm) - 1) - x; if (d < best) best = d; break; }
        }
    }
    return best;
}

// Scalar exact edge test on the target image (last-resort path, ~never runs).
__device__ bool edge_at(const float* __restrict__ img, int yy, int xx) {
    if (!(img[yy * W + xx] > 0.5f)) return false;
    #pragma unroll
    for (int dy = -1; dy <= 1; ++dy)
        #pragma unroll
        for (int dx = -1; dx <= 1; ++dx) {
            int y2 = yy + dy, x2 = xx + dx;
            if (y2 >= 0 && y2 < H && x2 >= 0 && x2 < W)
                if (!(img[y2 * W + x2] > 0.5f)) return true;   // some neighbor false
        }
    return false;
}

// ---------------------------------------------------------------------------
// Single-phase kernel, NO grid barrier, NO intermediate global array.
// Block = 8-row strip of one batch. Per block:
//  1. ballot masks for 34 target rows (+-13) and 10 pred rows (+-1)   [smem ~3KB]
//  2. edge masks: 32 strip target-edge rows (zeroed if row outside image),
//     8 pred-edge rows
//  3. per thread (column x): funnel-window g^2 for 16 middle rows,
//     r<=4 EDT in registers; escalation: strip-exact (<=169) then global 2D.
//  4. masked sqrt sum; ticket finalize.
// ---------------------------------------------------------------------------
__global__ void __launch_bounds__(256, 4) edge_loss_onephase(
        const float* __restrict__ pred,
        const float* __restrict__ targ,
        float* __restrict__ out) {
    const int bid  = blockIdx.x;          // 0..511
    const int tid  = threadIdx.x;         // 0..255 (column x)
    const int lane = tid & 31;
    const int wid  = tid >> 5;

    __shared__ u32 tmask[INROWS][8];      // target bool masks (rows y0-13..y0+20)
    __shared__ u32 pmask[TROWS + 2][8];   // pred bool masks (rows y0-1..y0+8)
    __shared__ u32 tepad[SROWS][10];      // target-edge masks, zero-padded words
    __shared__ u32 pe[TROWS][8];          // pred-edge masks
    __shared__ float wsum[8];
    __shared__ bool  amlast;

    const int b  = bid >> 5;
    const int y0 = (bid & 31) * TROWS;
    const float* tb_ = targ + b * H * W;
    const float* pb_ = pred + b * H * W;

    // 1. Ballot masks. OOB rows = all-true (never edge-triggering as neighbor).
    #pragma unroll
    for (int i = 0; i < INROWS; ++i) {
        int yy = y0 - (MARG + 1) + i;
        float v = (yy >= 0 && yy < H) ? tb_[yy * W + tid] : 1.0f;
        u32 m = __ballot_sync(0xFFFFFFFFu, v > 0.5f);
        if (lane == 0) tmask[i][wid] = m;
    }
    #pragma unroll
    for (int i = 0; i < TROWS + 2; ++i) {
        int yy = y0 - 1 + i;
        float v = (yy >= 0 && yy < H) ? pb_[yy * W + tid] : 1.0f;
        u32 m = __ballot_sync(0xFFFFFFFFu, v > 0.5f);
        if (lane == 0) pmask[i][wid] = m;
    }
    __syncthreads();

    // 2. Edge masks. 256 threads -> one (strip row, word) pair each.
    {
        int r = tid >> 3, w = tid & 7;          // r = 0..31
        int ys = y0 + r - MARG;                 // image row of strip row r
        u32 a9 = hand3(tmask[r], w) & hand3(tmask[r + 1], w) & hand3(tmask[r + 2], w);
        u32 te = tmask[r + 1][w] & ~a9;
        tepad[r][w + 1] = (ys >= 0 && ys < H) ? te : 0u;   // invalid rows: empty
    }
    if (tid < SROWS) { tepad[tid][0] = 0u; tepad[tid][9] = 0u; }
    if (tid < TROWS * 8) {
        int p = tid >> 3, w = tid & 7;
        u32 a9 = hand3(pmask[p], w) & hand3(pmask[p + 1], w) & hand3(pmask[p + 2], w);
        pe[p][w] = pmask[p + 1][w] & ~a9;
    }
    __syncthreads();

    // 3. Funnel-window g^2 for the 16 middle strip rows (j=8..23, rows y0-4..y0+11).
    // Window is exact for d <= 32; otherwise mark huge (resolved by escalation).
    const int wx = tid >> 5, bit = tid & 31;
    float g2f[16];
    #pragma unroll
    for (int j = 0; j < 16; ++j) {
        const u32* row = tepad[j + 8];
        u32 mlo = row[wx], mc = row[wx + 1], mhi = row[wx + 2];
        u64 lo = ((u64)mc << 32) | mlo;
        u64 hi = ((u64)mhi << 32) | mc;
        int dl = __clzll(lo << (31 - bit));                 // 64 if empty window
        u64 rsh = hi >> bit;
        int dr = rsh ? (__ffsll(rsh) - 1) : 1000;
        int d = min(dl, dr);
        g2f[j] = (d <= 32) ? (float)(d * d) : 1e12f;
    }

    // Per-pixel EDT (r<=4 candidates; all int-squared values exact in fp32).
    float acc = 0.0f;
    #pragma unroll
    for (int p = 0; p < TROWS; ++p) {
        u32 flag = (pe[p][wx] >> bit) & 1u;
        float d2 = g2f[p + 4];
        d2 = fminf(d2, 1.0f  + fminf(g2f[p + 3], g2f[p + 5]));
        d2 = fminf(d2, 4.0f  + fminf(g2f[p + 2], g2f[p + 6]));
        d2 = fminf(d2, 9.0f  + fminf(g2f[p + 1], g2f[p + 7]));
        d2 = fminf(d2, 16.0f + fminf(g2f[p],     g2f[p + 8]));
        // Exact iff d2 <= 25 (r>=5 candidates are >= 25; windowed-unknown rows
        // can only hold true candidates > 1024).
        bool need = flag && (d2 > 25.0f);
        if (__any_sync(0xFFFFFFFFu, need)) {
            if (need) {
                // Strip-exact: full-scan nearest over all 32 strip rows.
                float d2t = 1e30f;
                for (int j = 0; j < SROWS; ++j) {
                    int df = nearest_full(&tepad[j][1], tid);
                    if (df != 0x7FFFFFFF) {
                        int dy = p + MARG - j;
                        d2t = fminf(d2t, (float)(dy * dy + df * df));
                    }
                }
                if (d2t <= 169.0f) {
                    d2 = d2t;        // rows outside strip are >= 13^2 = 169: exact
                } else {
                    // Global exact 2D scan (probability ~0; correctness only).
                    float d2g = 1e6f * 1e6f;   // matches reference's BIG^2 exactly
                    int y = y0 + p;
                    for (int yy = 0; yy < H; ++yy)
                        for (int xx = 0; xx < W; ++xx)
                            if (edge_at(tb_, yy, xx)) {
                                int dy = y - yy, dx = tid - xx;
                                d2g = fminf(d2g, (float)(dy * dy + dx * dx));
                            }
                    d2 = d2g;
                }
            }
        }
        acc += flag ? sqrtf(d2) : 0.0f;
    }

    // 4. Block reduction (fp32, fixed order -> deterministic).
    #pragma unroll
    for (int o = 16; o; o >>= 1) acc += __shfl_down_sync(0xFFFFFFFFu, acc, o);
    if (lane == 0) wsum[wid] = acc;
    __syncthreads();
    if (tid == 0) {
        float s = wsum[0] + wsum[1] + wsum[2] + wsum[3]
                + wsum[4] + wsum[5] + wsum[6] + wsum[7];
        g_part[bid] = s;
        __threadfence();
        u32 t = atomicAdd(&g_tick, 1u);   // monotonic across graph replays
        amlast = ((t % NBLK) == (NBLK - 1));
    }
    __syncthreads();

    // Last-finished block reduces all partials (fixed order -> deterministic).
    if (amlast) {
        __threadfence();
        float v = g_part[tid] + g_part[tid + 256];
        #pragma unroll
        for (int o = 16; o; o >>= 1) v += __shfl_down_sync(0xFFFFFFFFu, v, o);
        if (lane == 0) wsum[wid] = v;
        __syncthreads();
        if (tid == 0) {
            double s = 0.0;
            #pragma unroll
            for (int i = 0; i < 8; ++i) s += (double)wsum[i];
            out[0] = (float)(s / (double)NPIX);
        }
    }
}

extern "C" void kernel_launch(void* const* d_in, const int* in_sizes, int n_in,
                              void* d_out, int out_size) {
    const float* pred = (const float*)d_in[0];
    const float* targ = (const float*)d_in[1];
    float* out = (float*)d_out;

    edge_loss_onephase<<<NBLK, 256>>>(pred, targ, out);
}

// round 17
// speedup vs baseline: 1.3898x; 1.0148x over previous
#include <cuda_runtime.h>
#include <math.h>

// Problem constants: pred/target are [16,1,256,256] fp32.
#define B 16
#define H 256
#define W 256
#define NPIX (B * H * W)   // 1048576
#define NBLK 512           // 16 batches x 32 row-strips of 8 rows
#define TROWS 8            // pixel rows per block
#define MARG 12            // vertical mask margin (strip-exact radius)
#define SROWS (TROWS + 2 * MARG)   // 32 strip mask rows
#define INROWS (SROWS + 2)         // 34 target input rows

typedef unsigned int u32;

// Device globals (no allocation allowed; zero-init at load).
__device__ float g_part[NBLK];
__device__ u32   g_tick;    // monotonic completion ticket

// Horizontal 3-AND of one u32 mask word with cross-word carries (OOB==true).
__device__ __forceinline__ u32 hand3(const u32* row, int w) {
    u32 m  = row[w];
    u32 lo = (w > 0) ? (row[w - 1] >> 31) : 1u;
    u32 hi = (w < 7) ? (row[w + 1] & 1u)  : 1u;
    return m & ((m << 1) | lo) & ((m >> 1) | (hi << 31));
}

// Exact full-scan nearest set-bit distance (8-word mask) or INT_MAX if empty.
__device__ __forceinline__ int nearest_full(const u32* __restrict__ mask, int x) {
    int best = 0x7FFFFFFF;
    const int wx = x >> 5, bit = x & 31;
    u32 m = mask[wx] & (0xFFFFFFFFu >> (31 - bit));
    if (m) {
        best = bit - (31 - __clz(m));
    } else {
        for (int w = wx - 1; w >= 0; --w) {
            u32 mm = mask[w];
            if (mm) { best = x - (w * 32 + 31 - __clz(mm)); break; }
        }
    }
    u32 m2 = mask[wx] & (0xFFFFFFFFu << bit);
    if (m2) {
        int d = (__ffs(m2) - 1) - bit;
        if (d < best) best = d;
    } else {
        for (int w = wx + 1; w < 8; ++w) {
            u32 mm = mask[w];
            if (mm) { int d = w * 32 + (__ffs(mm) - 1) - x; if (d < best) best = d; break; }
        }
    }
    return best;
}

// Scalar exact edge test on the target image (last-resort path, ~never runs).
__device__ bool edge_at(const float* __restrict__ img, int yy, int xx) {
    if (!(img[yy * W + xx] > 0.5f)) return false;
    #pragma unroll
    for (int dy = -1; dy <= 1; ++dy)
        #pragma unroll
        for (int dx = -1; dx <= 1; ++dx) {
            int y2 = yy + dy, x2 = xx + dx;
            if (y2 >= 0 && y2 < H && x2 >= 0 && x2 < W)
                if (!(img[y2 * W + x2] > 0.5f)) return true;   // some neighbor false
        }
    return false;
}

// ---------------------------------------------------------------------------
// Single-phase kernel, NO grid barrier, NO intermediate global array.
// Block = 8-row strip of one batch. Per block:
//  1. ballot masks for 34 target rows (+-13) and 10 pred rows (+-1)   [smem ~3KB]
//  2. edge masks: 32 strip target-edge rows, 8 pred-edge rows
//  3. per thread (column x): funnelshift-window g^2 for 16 middle rows,
//     r<=4 EDT in registers; escalation: strip-exact (<=169) then global 2D.
//  4. masked sqrt sum; ticket finalize.
// ---------------------------------------------------------------------------
__global__ void __launch_bounds__(256, 4) edge_loss_onephase(
        const float* __restrict__ pred,
        const float* __restrict__ targ,
        float* __restrict__ out) {
    const int bid  = blockIdx.x;          // 0..511
    const int tid  = threadIdx.x;         // 0..255 (column x)
    const int lane = tid & 31;
    const int wid  = tid >> 5;

    __shared__ u32 tmask[INROWS][8];      // target bool masks (rows y0-13..y0+20)
    __shared__ u32 pmask[TROWS + 2][8];   // pred bool masks (rows y0-1..y0+8)
    __shared__ u32 tepad[SROWS][10];      // target-edge masks, zero-padded words
    __shared__ u32 pe[TROWS][8];          // pred-edge masks
    __shared__ float wsum[8];
    __shared__ bool  amlast;

    const int b  = bid >> 5;
    const int y0 = (bid & 31) * TROWS;
    const float* tb_ = targ + b * H * W;
    const float* pb_ = pred + b * H * W;

    // 1. Ballot masks. OOB rows = all-true (never edge-triggering as neighbor).
    #pragma unroll
    for (int i = 0; i < INROWS; ++i) {
        int yy = y0 - (MARG + 1) + i;
        float v = (yy >= 0 && yy < H) ? tb_[yy * W + tid] : 1.0f;
        u32 m = __ballot_sync(0xFFFFFFFFu, v > 0.5f);
        if (lane == 0) tmask[i][wid] = m;
    }
    #pragma unroll
    for (int i = 0; i < TROWS + 2; ++i) {
        int yy = y0 - 1 + i;
        float v = (yy >= 0 && yy < H) ? pb_[yy * W + tid] : 1.0f;
        u32 m = __ballot_sync(0xFFFFFFFFu, v > 0.5f);
        if (lane == 0) pmask[i][wid] = m;
    }
    __syncthreads();

    // 2. Edge masks. 256 threads -> one (strip row, word) pair each.
    {
        int r = tid >> 3, w = tid & 7;          // r = 0..31
        int ys = y0 + r - MARG;                 // image row of strip row r
        u32 a9 = hand3(tmask[r], w) & hand3(tmask[r + 1], w) & hand3(tmask[r + 2], w);
        u32 te = tmask[r + 1][w] & ~a9;
        tepad[r][w + 1] = (ys >= 0 && ys < H) ? te : 0u;   // invalid rows: empty
    }
    if (tid < SROWS) { tepad[tid][0] = 0u; tepad[tid][9] = 0u; }
    if (tid < TROWS * 8) {
        int p = tid >> 3, w = tid & 7;
        u32 a9 = hand3(pmask[p], w) & hand3(pmask[p + 1], w) & hand3(pmask[p + 2], w);
        pe[p][w] = pmask[p + 1][w] & ~a9;
    }
    __syncthreads();

    // 3. Funnelshift-window g^2 for the 16 middle strip rows (rows y0-4..y0+11).
    // ul: 32-pixel left window (pixel x at MSB), ur: 32-pixel right window
    // (pixel x at LSB). Single SHF each. Exact for d <= 31; else huge
    // (resolved by escalation; only candidates <= 5 matter on the fast path).
    const int wx = tid >> 5, bit = tid & 31;
    float g2f[16];
    #pragma unroll
    for (int j = 0; j < 16; ++j) {
        const u32* row = tepad[j + 8];
        u32 mlo = row[wx], mc = row[wx + 1], mhi = row[wx + 2];
        u32 ul = __funnelshift_l(mlo, mc, 31 - bit);   // ((mc:mlo) << (31-bit)) hi word
        u32 ur = __funnelshift_r(mc, mhi, bit);        // ((mhi:mc) >> bit) lo word
        int dl = __clz(ul);                            // 32 if empty
        int dr = __ffs(ur) - 1;                        // -1 if empty
        int d = min(dl, (u32)dr < 32u ? dr : 64);      // empty right -> 64
        g2f[j] = (d <= 31) ? (float)(d * d) : 1e12f;
    }

    // Per-pixel EDT (r<=4 candidates; all int-squared values exact in fp32).
    float acc = 0.0f;
    #pragma unroll
    for (int p = 0; p < TROWS; ++p) {
        u32 flag = (pe[p][wx] >> bit) & 1u;
        float d2 = g2f[p + 4];
        d2 = fminf(d2, 1.0f  + fminf(g2f[p + 3], g2f[p + 5]));
        d2 = fminf(d2, 4.0f  + fminf(g2f[p + 2], g2f[p + 6]));
        d2 = fminf(d2, 9.0f  + fminf(g2f[p + 1], g2f[p + 7]));
        d2 = fminf(d2, 16.0f + fminf(g2f[p],     g2f[p + 8]));
        // Exact iff d2 <= 25 (r>=5 candidates are >= 25; windowed-unknown rows
        // can only hold true candidates > 961).
        bool need = flag && (d2 > 25.0f);
        if (__any_sync(0xFFFFFFFFu, need)) {
            if (need) {
                // Strip-exact: full-scan nearest over all 32 strip rows.
                float d2t = 1e30f;
                for (int j = 0; j < SROWS; ++j) {
                    int df = nearest_full(&tepad[j][1], tid);
                    if (df != 0x7FFFFFFF) {
                        int dy = p + MARG - j;
                        d2t = fminf(d2t, (float)(dy * dy + df * df));
                    }
                }
                if (d2t <= 169.0f) {
                    d2 = d2t;        // rows outside strip are >= 13^2 = 169: exact
                } else {
                    // Global exact 2D scan (probability ~0; correctness only).
                    float d2g = 1e6f * 1e6f;   // matches reference's BIG^2 exactly
                    int y = y0 + p;
                    for (int yy = 0; yy < H; ++yy)
                        for (int xx = 0; xx < W; ++xx)
                            if (edge_at(tb_, yy, xx)) {
                                int dy = y - yy, dx = tid - xx;
                                d2g = fminf(d2g, (float)(dy * dy + dx * dx));
                            }
                    d2 = d2g;
                }
            }
        }
        acc += flag ? sqrtf(d2) : 0.0f;
    }

    // 4. Block reduction (fp32, fixed order -> deterministic).
    #pragma unroll
    for (int o = 16; o; o >>= 1) acc += __shfl_down_sync(0xFFFFFFFFu, acc, o);
    if (lane == 0) wsum[wid] = acc;
    __syncthreads();
    if (tid == 0) {
        float s = wsum[0] + wsum[1] + wsum[2] + wsum[3]
                + wsum[4] + wsum[5] + wsum[6] + wsum[7];
        g_part[bid] = s;
        __threadfence();
        u32 t = atomicAdd(&g_tick, 1u);   // monotonic across graph replays
        amlast = ((t % NBLK) == (NBLK - 1));
    }
    __syncthreads();

    // Last-finished block reduces all partials (fixed order -> deterministic).
    if (amlast) {
        __threadfence();
        float v = g_part[tid] + g_part[tid + 256];
        #pragma unroll
        for (int o = 16; o; o >>= 1) v += __shfl_down_sync(0xFFFFFFFFu, v, o);
        if (lane == 0) wsum[wid] = v;
        __syncthreads();
        if (tid == 0) {
            double s = 0.0;
            #pragma unroll
            for (int i = 0; i < 8; ++i) s += (double)wsum[i];
            out[0] = (float)(s / (double)NPIX);
        }
    }
}

extern "C" void kernel_launch(void* const* d_in, const int* in_sizes, int n_in,
                              void* d_out, int out_size) {
    const float* pred = (const float*)d_in[0];
    const float* targ = (const float*)d_in[1];
    float* out = (float*)d_out;

    edge_loss_onephase<<<NBLK, 256>>>(pred, targ, out);
}